// round 13
// baseline (speedup 1.0000x reference)
#include <cuda_runtime.h>
#include <cuda_fp16.h>

#define NV 5
#define NC 32
#define ND 48
#define NH 128
#define NW 160
#define HW (NH*NW)        /* 20480 */
#define DHW (ND*HW)       /* 983040 */
#define RATIO 8
#define NTASK (5*NH*2)    /* (w-strips) * h * depth-halves = 1280 */

typedef unsigned long long ull;

// ---- packed f32x2 helpers (Blackwell FFMA2 — only reachable via PTX) ----
__device__ __forceinline__ ull pack2(float lo, float hi) {
    ull r; asm("mov.b64 %0, {%1, %2};" : "=l"(r) : "f"(lo), "f"(hi)); return r;
}
__device__ __forceinline__ float2 unpack2(ull v) {
    float2 f; asm("mov.b64 {%0, %1}, %2;" : "=f"(f.x), "=f"(f.y) : "l"(v)); return f;
}
__device__ __forceinline__ ull fma2(ull a, ull b, ull c) {
    ull r; asm("fma.rn.f32x2 %0, %1, %2, %3;" : "=l"(r) : "l"(a), "l"(b), "l"(c)); return r;
}
__device__ __forceinline__ ull mul2(ull a, ull b) {
    ull r; asm("mul.rn.f32x2 %0, %1, %2;" : "=l"(r) : "l"(a), "l"(b)); return r;
}
__device__ __forceinline__ ull add2(ull a, ull b) {
    ull r; asm("add.rn.f32x2 %0, %1, %2;" : "=l"(r) : "l"(a), "l"(b)); return r;
}

// Scratch (device globals — no allocation allowed)
__device__ float g_feat[NV*HW*NC];          // (v, h, w, c) channels-last fp32, 13.1 MB
__device__ float g_B[(size_t)9*DHW];        // 9 hw-tap fields (kd folded), 35.4 MB
__device__ float g_pre[DHW];                // (d, h, w), 3.9 MB
__device__ float g_rot[NV][9];
__device__ float g_trans[NV][3];
__device__ int   g_ctr;                     // work-stealing task counter

// ---------------------------------------------------------------------------
// 1) Projection setup (double precision) + task-counter reset
// ---------------------------------------------------------------------------
__global__ void proj_kernel(const float* __restrict__ proj) {
    if (threadIdx.x != 0) return;
    g_ctr = 0;
    double comb[NV][16];
    for (int v = 0; v < NV; v++) {
        const float* E = proj + v*32;
        const float* P = proj + v*32 + 16;
        for (int r = 0; r < 3; r++)
            for (int c = 0; c < 4; c++) {
                double s = 0.0;
                for (int k = 0; k < 3; k++) s += (double)P[r*4+k] * (double)E[k*4+c];
                comb[v][r*4+c] = s;
            }
        for (int c = 0; c < 4; c++) comb[v][12+c] = (double)E[12+c];
    }
    double a[4][8];
    for (int i = 0; i < 4; i++)
        for (int j = 0; j < 4; j++) { a[i][j] = comb[0][i*4+j]; a[i][4+j] = (i==j) ? 1.0 : 0.0; }
    for (int col = 0; col < 4; col++) {
        int p = col;
        for (int r = col+1; r < 4; r++) if (fabs(a[r][col]) > fabs(a[p][col])) p = r;
        if (p != col) for (int j = 0; j < 8; j++) { double t = a[col][j]; a[col][j] = a[p][j]; a[p][j] = t; }
        double inv = 1.0 / a[col][col];
        for (int j = 0; j < 8; j++) a[col][j] *= inv;
        for (int r = 0; r < 4; r++) if (r != col) {
            double f = a[r][col];
            for (int j = 0; j < 8; j++) a[r][j] -= f * a[col][j];
        }
    }
    for (int v = 1; v < NV; v++) {
        double Pm[16];
        for (int i = 0; i < 4; i++)
            for (int j = 0; j < 4; j++) {
                double s = 0.0;
                for (int k = 0; k < 4; k++) s += comb[v][i*4+k] * a[k][4+j];
                Pm[i*4+j] = s;
            }
        for (int i = 0; i < 3; i++) {
            for (int j = 0; j < 3; j++) g_rot[v][i*3+j] = (float)Pm[i*4+j];
            g_trans[v][i] = (float)Pm[i*4+3];
        }
    }
}

// ---------------------------------------------------------------------------
// 2) Features (V,C,H,W) -> (V,H,W,C) channels-last (fp32), split over views
// ---------------------------------------------------------------------------
__global__ __launch_bounds__(256) void transpose_kernel(const float* __restrict__ f, int v0) {
    __shared__ float t[32][33];
    int w0 = blockIdx.x * 32, h = blockIdx.y, v = blockIdx.z + v0;
    int tid = threadIdx.x;
    #pragma unroll
    for (int e = tid; e < 1024; e += 256) {
        int c = e >> 5, w = e & 31;
        t[c][w] = f[((size_t)(v*NC + c)*NH + h)*NW + w0 + w];
    }
    __syncthreads();
    #pragma unroll
    for (int e = tid; e < 1024; e += 256) {
        int w = e >> 5, c = e & 31;
        g_feat[((size_t)((v*NH + h)*NW) + w0 + w)*NC + c] = t[c][w];
    }
}

// ---------------------------------------------------------------------------
// 3) FUSED warp+variance+contraction+kd-fold — PERSISTENT, WARP-SPECIALIZED,
//    half2 variance exchange + PACKED f32x2 (FFMA2) arithmetic in both hot
//    loops.  444 CTAs, 9 warps: warp 8 = producer (bilinear params for d+1),
//    warps 0..7 gather depth d; all warps run Phase B (tap9 = wid) with
//    ring accumulators folding conv's kd.  One barrier per depth.
// ---------------------------------------------------------------------------
__global__ __launch_bounds__(288, 3) void warpvar_kernel(const float* __restrict__ dvals,
                                                         const float* __restrict__ Wreg) {
    int tid  = threadIdx.x;
    int lane = tid & 31, wid = tid >> 5;     // wid 0..8
    int sub = lane >> 3, q = lane & 7;
    int p  = wid * 4 + sub;                  // point 0..31 (gather warps)
    bool doA = (wid < 8);

    __shared__ __align__(16) float swt[9][3][NC];   // [tap9][kd][c]
    __shared__ float sdep[ND];
    __shared__ __half2 svh[2][16][34];       // variance, packed channel pairs
    __shared__ float4 spw[2][NV-1][32];      // staged bilinear weights
    __shared__ int4   spo[2][NV-1][32];      // staged gather offsets (16B units)
    __shared__ int s_task;

    for (int e = tid; e < 9*3*NC; e += 288) {
        int c = e & 31; int kd = (e >> 5) % 3; int t9 = e / 96;
        swt[t9][kd][c] = Wreg[c*27 + kd*9 + t9];
    }
    if (tid < ND) sdep[tid] = dvals[tid];

    // weight pairs for Phase B, read as 16B chunks (2 channel-pairs each)
    const ulonglong2* W0 = (const ulonglong2*)&swt[wid][0][0];
    const ulonglong2* W1 = (const ulonglong2*)&swt[wid][1][0];
    const ulonglong2* W2 = (const ulonglong2*)&swt[wid][2][0];
    const float inv5 = 1.f / (float)NV;

    while (true) {
        if (tid == 0) s_task = atomicAdd(&g_ctr, 1);
        __syncthreads();                     // also orders swt/sdep on first pass
        int t = s_task;
        if (t >= NTASK) break;

        int dhalf = t & 1;
        int strip = t >> 1;
        int w0 = (strip % 5) * 32;
        int h  = strip / 5;

        int odlo = dhalf * (ND/2), odhi = odlo + ND/2 - 1;
        int dlo = (odlo - 1 < 0) ? 0 : odlo - 1;
        int dhi = (odhi + 1 > ND-1) ? ND-1 : odhi + 1;

        // ---- producer state: warp 8, lane = point ----
        float rx[NV-1], ry[NV-1], rz[NV-1], tcx[NV-1], tcy[NV-1], tcz[NV-1];
        if (!doA) {
            float fw = (float)(w0 + lane), fh = (float)h;
            #pragma unroll
            for (int v = 1; v < NV; v++) {
                const float* R = g_rot[v];
                const float* T = g_trans[v];
                rx[v-1] = R[0]*fw + R[1]*fh + R[2];
                ry[v-1] = R[3]*fw + R[4]*fh + R[5];
                rz[v-1] = R[6]*fw + R[7]*fh + R[8];
                tcx[v-1] = T[0]; tcy[v-1] = T[1]; tcz[v-1] = T[2];
            }
        }
        auto produce = [&](int pb, float dep) {
            #pragma unroll
            for (int v = 0; v < NV-1; v++) {
                float px = rx[v]*dep + tcx[v];
                float py = ry[v]*dep + tcy[v];
                float pz = rz[v]*dep + tcz[v];
                float rzi = __fdividef(1.f, pz);
                float gx = px * rzi, gy = py * rzi;
                float x0f = floorf(gx), y0f = floorf(gy);
                float wx = gx - x0f, wy = gy - y0f;
                float x1f = x0f + 1.f, y1f = y0f + 1.f;
                float vx0 = (x0f >= 0.f && x0f <= (float)(NW-1)) ? 1.f : 0.f;
                float vx1 = (x1f >= 0.f && x1f <= (float)(NW-1)) ? 1.f : 0.f;
                float vy0 = (y0f >= 0.f && y0f <= (float)(NH-1)) ? 1.f : 0.f;
                float vy1 = (y1f >= 0.f && y1f <= (float)(NH-1)) ? 1.f : 0.f;
                float w00 = (1.f-wx)*(1.f-wy) * vx0 * vy0;
                float w10 = wx*(1.f-wy)       * vx1 * vy0;
                float w01 = (1.f-wx)*wy       * vx0 * vy1;
                float w11 = wx*wy             * vx1 * vy1;
                int x0 = (int)fminf(fmaxf(x0f, 0.f), (float)(NW-1));
                int x1 = (int)fminf(fmaxf(x1f, 0.f), (float)(NW-1));
                int y0 = (int)fminf(fmaxf(y0f, 0.f), (float)(NH-1));
                int y1 = (int)fminf(fmaxf(y1f, 0.f), (float)(NH-1));
                int ox0 = x0*8, ox1 = x1*8;                 // 16B units
                int oy0 = y0*(NW*8), oy1 = y1*(NW*8);
                spw[pb][v][lane] = make_float4(w00, w10, w01, w11);
                spo[pb][v][lane] = make_int4(oy0+ox0, oy0+ox1, oy1+ox0, oy1+ox1);
            }
        };

        // ---- gather state: reference view (depth-independent), packed ----
        ull ref01 = 0, ref23 = 0, ref2_01 = 0, ref2_23 = 0;
        if (doA) {
            int w = w0 + p;
            float4 ref = ((const float4*)(g_feat + (size_t)(h*NW + w)*NC))[q];
            ref01 = pack2(ref.x, ref.y);
            ref23 = pack2(ref.z, ref.w);
            ref2_01 = mul2(ref01, ref01);
            ref2_23 = mul2(ref23, ref23);
        }

        if (!doA) produce(dlo & 1, sdep[dlo]);
        __syncthreads();

        float aP = 0.f, aC = 0.f, aN = 0.f;
        const size_t hwbase = (size_t)h*NW + w0 + lane;

        for (int d = dlo; d <= dhi; d++) {
            int buf = d & 1;
            if (doA) {
                ull vs01 = ref01, vs23 = ref23;
                ull vq01 = ref2_01, vq23 = ref2_23;
                #pragma unroll
                for (int v = 0; v < NV-1; v++) {
                    float4 wts = spw[buf][v][p];       // broadcast LDS.128
                    int4   of  = spo[buf][v][p];
                    const ulonglong2* base = (const ulonglong2*)g_feat + (size_t)(v+1)*HW*8;
                    ull wv01 = 0, wv23 = 0;            // two packed +0.f
                    if (wts.x + wts.y > 1e-4f) {
                        ulonglong2 a = base[of.x + q];
                        ulonglong2 b = base[of.y + q];
                        ull w00s = pack2(wts.x, wts.x), w10s = pack2(wts.y, wts.y);
                        wv01 = fma2(w10s, b.x, mul2(w00s, a.x));
                        wv23 = fma2(w10s, b.y, mul2(w00s, a.y));
                    }
                    if (wts.z + wts.w > 1e-4f) {
                        ulonglong2 c4 = base[of.z + q];
                        ulonglong2 e4 = base[of.w + q];
                        ull w01s = pack2(wts.z, wts.z), w11s = pack2(wts.w, wts.w);
                        wv01 = fma2(w01s, c4.x, wv01);
                        wv01 = fma2(w11s, e4.x, wv01);
                        wv23 = fma2(w01s, c4.y, wv23);
                        wv23 = fma2(w11s, e4.y, wv23);
                    }
                    vs01 = add2(vs01, wv01); vs23 = add2(vs23, wv23);
                    vq01 = fma2(wv01, wv01, vq01); vq23 = fma2(wv23, wv23, vq23);
                }
                float2 s01 = unpack2(vs01), s23 = unpack2(vs23);
                float2 q01 = unpack2(vq01), q23 = unpack2(vq23);
                float mx = s01.x*inv5, my = s01.y*inv5, mz = s23.x*inv5, mw = s23.y*inv5;
                float2 v01 = make_float2(q01.x*inv5 - mx*mx, q01.y*inv5 - my*my);
                float2 v23 = make_float2(q23.x*inv5 - mz*mz, q23.y*inv5 - mw*mw);
                svh[buf][2*q+0][p] = __float22half2_rn(v01);
                svh[buf][2*q+1][p] = __float22half2_rn(v23);
            } else {
                if (d < dhi) produce((d+1) & 1, sdep[d+1]);
            }
            __syncthreads();

            // Phase B: 3 kd-dots for tap9 = wid, packed f32x2 accumulation
            ull d0p = 0, d1p = 0, d2p = 0;
            #pragma unroll
            for (int c4 = 0; c4 < 8; c4++) {
                float2 fa = __half22float2(svh[buf][2*c4+0][lane]);
                float2 fb = __half22float2(svh[buf][2*c4+1][lane]);
                ull fap = pack2(fa.x, fa.y), fbp = pack2(fb.x, fb.y);
                ulonglong2 u0 = W0[c4], u1 = W1[c4], u2 = W2[c4];
                d0p = fma2(fap, u0.x, d0p); d0p = fma2(fbp, u0.y, d0p);
                d1p = fma2(fap, u1.x, d1p); d1p = fma2(fbp, u1.y, d1p);
                d2p = fma2(fap, u2.x, d2p); d2p = fma2(fbp, u2.y, d2p);
            }
            float2 e0 = unpack2(d0p), e1 = unpack2(d1p), e2 = unpack2(d2p);
            aN += e0.x + e0.y;                    // od = d+1
            aC += e1.x + e1.y;                    // od = d
            aP += e2.x + e2.y;                    // od = d-1
            int od = d - 1;
            if (od >= odlo && od <= odhi)
                g_B[(size_t)wid*DHW + (size_t)od*HW + hwbase] = aP;
            aP = aC; aC = aN; aN = 0.f;
        }
        if (odhi == ND-1)
            g_B[(size_t)wid*DHW + (size_t)(ND-1)*HW + hwbase] = aP;
    }
}

// ---------------------------------------------------------------------------
// 4) 9-tap shifted sum over (h,w): pre[d,h,w] = sum_{kh,kw} B_t[d,h+kh-1,w+kw-1]
// ---------------------------------------------------------------------------
__global__ __launch_bounds__(256) void gathersum_kernel() {
    int w = blockIdx.x*32 + threadIdx.x;
    int h = blockIdx.y*8  + threadIdx.y;
    int d = blockIdx.z;
    float s = 0.f;
    #pragma unroll
    for (int kh = 0; kh < 3; kh++) {
        int hh = h + kh - 1;
        if (hh < 0 || hh >= NH) continue;
        size_t rowb = (size_t)d*HW + (size_t)hh*NW;
        #pragma unroll
        for (int kw = 0; kw < 3; kw++) {
            int ww = w + kw - 1;
            if (ww < 0 || ww >= NW) continue;
            int t = kh*3 + kw;
            s += g_B[(size_t)t*DHW + rowb + ww];
        }
    }
    g_pre[(size_t)d*HW + (size_t)h*NW + w] = s;
}

// ---------------------------------------------------------------------------
// 5) Softmax over D + depth regression + confidence
// ---------------------------------------------------------------------------
__global__ __launch_bounds__(256) void sdc_kernel(const float* __restrict__ dvals,
                                                  float* __restrict__ odepth,
                                                  float* __restrict__ oconf) {
    int idx = blockIdx.x*blockDim.x + threadIdx.x;
    if (idx >= HW) return;
    float p[ND];
    float mx = -1e30f;
    #pragma unroll
    for (int dd = 0; dd < ND; dd++) { p[dd] = g_pre[(size_t)dd*HW + idx]; mx = fmaxf(mx, p[dd]); }
    float s = 0.f;
    #pragma unroll
    for (int dd = 0; dd < ND; dd++) { p[dd] = expf(p[dd] - mx); s += p[dd]; }
    float inv = 1.f / s;
    float depth = 0.f, fi = 0.f;
    #pragma unroll
    for (int dd = 0; dd < ND; dd++) {
        float pr = p[dd] * inv;
        depth += pr * dvals[dd];
        fi    += pr * (float)dd;
    }
    int di = (int)fi;
    di = max(0, min(ND-1, di));
    float conf = 0.f;
    #pragma unroll
    for (int dd = 0; dd < ND; dd++)
        if (dd >= di-1 && dd <= di+2) conf += p[dd] * inv;
    odepth[idx] = depth;
    oconf[idx]  = conf;
}

// ---------------------------------------------------------------------------
// 6) Convex upsample x8
// ---------------------------------------------------------------------------
__global__ __launch_bounds__(256) void upsample_kernel(const float* __restrict__ mask,
                                                       const float* __restrict__ depth,
                                                       float* __restrict__ out) {
    int idx = blockIdx.x*blockDim.x + threadIdx.x;
    if (idx >= RATIO*HW) return;
    int i   = idx / HW;
    int rem = idx - i*HW;
    int h   = rem / NW;
    int w   = rem - h*NW;

    float nb[9];
    #pragma unroll
    for (int dy = 0; dy < 3; dy++)
        #pragma unroll
        for (int dx = 0; dx < 3; dx++) {
            int hh = h + dy - 1, ww = w + dx - 1;
            nb[dy*3+dx] = (hh >= 0 && hh < NH && ww >= 0 && ww < NW) ? depth[hh*NW + ww] : 0.f;
        }

    float val[8];
    #pragma unroll
    for (int j = 0; j < 8; j++) {
        float m[9]; float mx = -1e30f;
        #pragma unroll
        for (int k = 0; k < 9; k++) {
            m[k] = mask[(size_t)((k*8 + i)*8 + j)*HW + rem];
            mx = fmaxf(mx, m[k]);
        }
        float s = 0.f, acc = 0.f;
        #pragma unroll
        for (int k = 0; k < 9; k++) {
            float e = __expf(m[k] - mx);
            s += e; acc += e * nb[k];
        }
        val[j] = acc / s;
    }
    float* o = out + (size_t)(h*8 + i)*(NW*8) + w*8;
    float4* o4 = (float4*)o;
    o4[0] = make_float4(val[0], val[1], val[2], val[3]);
    o4[1] = make_float4(val[4], val[5], val[6], val[7]);
}

// ---------------------------------------------------------------------------
extern "C" void kernel_launch(void* const* d_in, const int* in_sizes, int n_in,
                              void* d_out, int out_size) {
    const float* features = (const float*)d_in[0];  // (V,B,C,H,W)
    const float* proj     = (const float*)d_in[1];  // (B,V,2,4,4)
    const float* dvals    = (const float*)d_in[2];  // (B,D)
    const float* mask     = (const float*)d_in[3];  // (B,576,H,W)
    const float* Wreg     = (const float*)d_in[4];  // (1,C,3,3,3)

    float* out       = (float*)d_out;
    float* out_depth = out + (size_t)NH*RATIO*NW*RATIO;   // after depth_up
    float* out_conf  = out_depth + HW;

    proj_kernel<<<1, 32>>>(proj);                                    // launch 1 (+ctr reset)
    transpose_kernel<<<dim3(NW/32, NH, 2), 256>>>(features, 0);      // launch 2
    transpose_kernel<<<dim3(NW/32, NH, 3), 256>>>(features, 2);      // launch 3
    warpvar_kernel<<<444, 288>>>(dvals, Wreg);                       // launch 4 (ncu slot)
    gathersum_kernel<<<dim3(NW/32, NH/8, ND), dim3(32, 8)>>>();      // launch 5
    sdc_kernel<<<HW/256, 256>>>(dvals, out_depth, out_conf);         // launch 6
    upsample_kernel<<<(RATIO*HW)/256, 256>>>(mask, out_depth, out);  // launch 7
}

// round 14
// speedup vs baseline: 1.0389x; 1.0389x over previous
#include <cuda_runtime.h>
#include <cuda_fp16.h>

#define NV 5
#define NC 32
#define ND 48
#define NH 128
#define NW 160
#define HW (NH*NW)        /* 20480 */
#define DHW (ND*HW)       /* 983040 */
#define RATIO 8
#define NTASK (5*NH*2)    /* (w-strips) * h * depth-halves = 1280 */

// Scratch (device globals — no allocation allowed)
__device__ float g_feat[NV*HW*NC];          // (v, h, w, c) channels-last fp32, 13.1 MB
__device__ float g_B[(size_t)9*DHW];        // 9 hw-tap fields (kd folded), 35.4 MB
__device__ float g_pre[DHW];                // (d, h, w), 3.9 MB
__device__ float g_rot[NV][9];
__device__ float g_trans[NV][3];
__device__ int   g_ctr;                     // work-stealing task counter

// ---------------------------------------------------------------------------
// 1) Projection setup (double precision) + task-counter reset
// ---------------------------------------------------------------------------
__global__ void proj_kernel(const float* __restrict__ proj) {
    if (threadIdx.x != 0) return;
    g_ctr = 0;
    double comb[NV][16];
    for (int v = 0; v < NV; v++) {
        const float* E = proj + v*32;
        const float* P = proj + v*32 + 16;
        for (int r = 0; r < 3; r++)
            for (int c = 0; c < 4; c++) {
                double s = 0.0;
                for (int k = 0; k < 3; k++) s += (double)P[r*4+k] * (double)E[k*4+c];
                comb[v][r*4+c] = s;
            }
        for (int c = 0; c < 4; c++) comb[v][12+c] = (double)E[12+c];
    }
    double a[4][8];
    for (int i = 0; i < 4; i++)
        for (int j = 0; j < 4; j++) { a[i][j] = comb[0][i*4+j]; a[i][4+j] = (i==j) ? 1.0 : 0.0; }
    for (int col = 0; col < 4; col++) {
        int p = col;
        for (int r = col+1; r < 4; r++) if (fabs(a[r][col]) > fabs(a[p][col])) p = r;
        if (p != col) for (int j = 0; j < 8; j++) { double t = a[col][j]; a[col][j] = a[p][j]; a[p][j] = t; }
        double inv = 1.0 / a[col][col];
        for (int j = 0; j < 8; j++) a[col][j] *= inv;
        for (int r = 0; r < 4; r++) if (r != col) {
            double f = a[r][col];
            for (int j = 0; j < 8; j++) a[r][j] -= f * a[col][j];
        }
    }
    for (int v = 1; v < NV; v++) {
        double Pm[16];
        for (int i = 0; i < 4; i++)
            for (int j = 0; j < 4; j++) {
                double s = 0.0;
                for (int k = 0; k < 4; k++) s += comb[v][i*4+k] * a[k][4+j];
                Pm[i*4+j] = s;
            }
        for (int i = 0; i < 3; i++) {
            for (int j = 0; j < 3; j++) g_rot[v][i*3+j] = (float)Pm[i*4+j];
            g_trans[v][i] = (float)Pm[i*4+3];
        }
    }
}

// ---------------------------------------------------------------------------
// 2) Features (V,C,H,W) -> (V,H,W,C) channels-last (fp32), split over views
// ---------------------------------------------------------------------------
__global__ __launch_bounds__(256) void transpose_kernel(const float* __restrict__ f, int v0) {
    __shared__ float t[32][33];
    int w0 = blockIdx.x * 32, h = blockIdx.y, v = blockIdx.z + v0;
    int tid = threadIdx.x;
    #pragma unroll
    for (int e = tid; e < 1024; e += 256) {
        int c = e >> 5, w = e & 31;
        t[c][w] = f[((size_t)(v*NC + c)*NH + h)*NW + w0 + w];
    }
    __syncthreads();
    #pragma unroll
    for (int e = tid; e < 1024; e += 256) {
        int w = e >> 5, c = e & 31;
        g_feat[((size_t)((v*NH + h)*NW) + w0 + w)*NC + c] = t[c][w];
    }
}

// ---------------------------------------------------------------------------
// 3) FUSED warp+variance+contraction+kd-fold — PERSISTENT, WARP-SPECIALIZED,
//    half2 variance exchange.  R12 body; register diet for 4 CTAs/SM:
//    rot/trans live in smem and the producer recomputes its per-view
//    coefficients inside each produce() call (kills a 24-reg live range).
// ---------------------------------------------------------------------------
__global__ __launch_bounds__(288, 4) void warpvar_kernel(const float* __restrict__ dvals,
                                                         const float* __restrict__ Wreg) {
    int tid  = threadIdx.x;
    int lane = tid & 31, wid = tid >> 5;     // wid 0..8
    int sub = lane >> 3, q = lane & 7;
    int p  = wid * 4 + sub;                  // point 0..31 (gather warps)
    bool doA = (wid < 8);

    __shared__ float swt[9][3][NC];          // [tap9][kd][c]
    __shared__ float sdep[ND];
    __shared__ float srot[NV-1][9];          // per-view rotation (views 1..4)
    __shared__ float strn[NV-1][3];          // per-view translation
    __shared__ __half2 svh[2][16][34];       // variance, packed channel pairs
    __shared__ float4 spw[2][NV-1][32];      // staged bilinear weights
    __shared__ int4   spo[2][NV-1][32];      // staged gather offsets (16B units)
    __shared__ int s_task;

    for (int e = tid; e < 9*3*NC; e += 288) {
        int c = e & 31; int kd = (e >> 5) % 3; int t9 = e / 96;
        swt[t9][kd][c] = Wreg[c*27 + kd*9 + t9];
    }
    if (tid < ND) sdep[tid] = dvals[tid];
    if (tid < (NV-1)*9) srot[tid/9][tid%9] = g_rot[tid/9 + 1][tid%9];
    if (tid < (NV-1)*3) strn[tid/3][tid%3] = g_trans[tid/3 + 1][tid%3];

    const float4* wk0 = (const float4*)&swt[wid][0][0];
    const float4* wk1 = (const float4*)&swt[wid][1][0];
    const float4* wk2 = (const float4*)&swt[wid][2][0];
    const float inv5 = 1.f / (float)NV;

    while (true) {
        if (tid == 0) s_task = atomicAdd(&g_ctr, 1);
        __syncthreads();                     // also orders smem init on first pass
        int t = s_task;
        if (t >= NTASK) break;

        int dhalf = t & 1;
        int strip = t >> 1;
        int w0 = (strip % 5) * 32;
        int h  = strip / 5;

        int odlo = dhalf * (ND/2), odhi = odlo + ND/2 - 1;
        int dlo = (odlo - 1 < 0) ? 0 : odlo - 1;
        int dhi = (odhi + 1 > ND-1) ? ND-1 : odhi + 1;

        // producer: recompute per-view coefficients per call (no long-lived regs)
        auto produce = [&](int pb, float dep) {
            float fw = (float)(w0 + lane), fh = (float)h;
            #pragma unroll
            for (int v = 0; v < NV-1; v++) {
                const float* R = srot[v];
                const float* T = strn[v];
                float px = (R[0]*fw + R[1]*fh + R[2]) * dep + T[0];
                float py = (R[3]*fw + R[4]*fh + R[5]) * dep + T[1];
                float pz = (R[6]*fw + R[7]*fh + R[8]) * dep + T[2];
                float rzi = __fdividef(1.f, pz);
                float gx = px * rzi, gy = py * rzi;
                float x0f = floorf(gx), y0f = floorf(gy);
                float wx = gx - x0f, wy = gy - y0f;
                float x1f = x0f + 1.f, y1f = y0f + 1.f;
                float vx0 = (x0f >= 0.f && x0f <= (float)(NW-1)) ? 1.f : 0.f;
                float vx1 = (x1f >= 0.f && x1f <= (float)(NW-1)) ? 1.f : 0.f;
                float vy0 = (y0f >= 0.f && y0f <= (float)(NH-1)) ? 1.f : 0.f;
                float vy1 = (y1f >= 0.f && y1f <= (float)(NH-1)) ? 1.f : 0.f;
                float w00 = (1.f-wx)*(1.f-wy) * vx0 * vy0;
                float w10 = wx*(1.f-wy)       * vx1 * vy0;
                float w01 = (1.f-wx)*wy       * vx0 * vy1;
                float w11 = wx*wy             * vx1 * vy1;
                int x0 = (int)fminf(fmaxf(x0f, 0.f), (float)(NW-1));
                int x1 = (int)fminf(fmaxf(x1f, 0.f), (float)(NW-1));
                int y0 = (int)fminf(fmaxf(y0f, 0.f), (float)(NH-1));
                int y1 = (int)fminf(fmaxf(y1f, 0.f), (float)(NH-1));
                int ox0 = x0*8, ox1 = x1*8;                 // float4 units
                int oy0 = y0*(NW*8), oy1 = y1*(NW*8);
                spw[pb][v][lane] = make_float4(w00, w10, w01, w11);
                spo[pb][v][lane] = make_int4(oy0+ox0, oy0+ox1, oy1+ox0, oy1+ox1);
            }
        };

        // ---- gather state: reference view (depth-independent) ----
        float4 ref, ref2;
        if (doA) {
            int w = w0 + p;
            ref = ((const float4*)(g_feat + (size_t)(h*NW + w)*NC))[q];
            ref2 = make_float4(ref.x*ref.x, ref.y*ref.y, ref.z*ref.z, ref.w*ref.w);
        }

        if (!doA) produce(dlo & 1, sdep[dlo]);
        __syncthreads();

        float aP = 0.f, aC = 0.f, aN = 0.f;
        const size_t hwbase = (size_t)h*NW + w0 + lane;

        for (int d = dlo; d <= dhi; d++) {
            int buf = d & 1;
            if (doA) {
                float4 vs = ref, vq = ref2;
                #pragma unroll
                for (int v = 0; v < NV-1; v++) {
                    float4 wts = spw[buf][v][p];       // broadcast LDS.128
                    int4   of  = spo[buf][v][p];
                    const float4* base = (const float4*)g_feat + (size_t)(v+1)*HW*8;
                    float4 wv = make_float4(0.f, 0.f, 0.f, 0.f);
                    if (wts.x + wts.y > 1e-4f) {
                        float4 a = base[of.x + q];
                        float4 b = base[of.y + q];
                        wv.x = wts.x*a.x + wts.y*b.x;
                        wv.y = wts.x*a.y + wts.y*b.y;
                        wv.z = wts.x*a.z + wts.y*b.z;
                        wv.w = wts.x*a.w + wts.y*b.w;
                    }
                    if (wts.z + wts.w > 1e-4f) {
                        float4 c4 = base[of.z + q];
                        float4 e4 = base[of.w + q];
                        wv.x += wts.z*c4.x + wts.w*e4.x;
                        wv.y += wts.z*c4.y + wts.w*e4.y;
                        wv.z += wts.z*c4.z + wts.w*e4.z;
                        wv.w += wts.z*c4.w + wts.w*e4.w;
                    }
                    vs.x += wv.x; vs.y += wv.y; vs.z += wv.z; vs.w += wv.w;
                    vq.x += wv.x*wv.x; vq.y += wv.y*wv.y; vq.z += wv.z*wv.z; vq.w += wv.w*wv.w;
                }
                float mx = vs.x*inv5, my = vs.y*inv5, mz = vs.z*inv5, mw = vs.w*inv5;
                float2 v01 = make_float2(vq.x*inv5 - mx*mx, vq.y*inv5 - my*my);
                float2 v23 = make_float2(vq.z*inv5 - mz*mz, vq.w*inv5 - mw*mw);
                svh[buf][2*q+0][p] = __float22half2_rn(v01);
                svh[buf][2*q+1][p] = __float22half2_rn(v23);
            } else {
                if (d < dhi) produce((d+1) & 1, sdep[d+1]);
            }
            __syncthreads();

            // Phase B: 3 kd-dots for tap9 = wid; sv read as half2 (16 LDS.32)
            float d0 = 0.f, d1 = 0.f, d2 = 0.f;
            #pragma unroll
            for (int c4 = 0; c4 < 8; c4++) {
                float2 fa = __half22float2(svh[buf][2*c4+0][lane]);
                float2 fb = __half22float2(svh[buf][2*c4+1][lane]);
                float4 u0 = wk0[c4], u1 = wk1[c4], u2 = wk2[c4];
                d0 += fa.x*u0.x + fa.y*u0.y + fb.x*u0.z + fb.y*u0.w;
                d1 += fa.x*u1.x + fa.y*u1.y + fb.x*u1.z + fb.y*u1.w;
                d2 += fa.x*u2.x + fa.y*u2.y + fb.x*u2.z + fb.y*u2.w;
            }
            aN += d0; aC += d1; aP += d2;        // od = d+1, d, d-1
            int od = d - 1;
            if (od >= odlo && od <= odhi)
                g_B[(size_t)wid*DHW + (size_t)od*HW + hwbase] = aP;
            aP = aC; aC = aN; aN = 0.f;
        }
        if (odhi == ND-1)
            g_B[(size_t)wid*DHW + (size_t)(ND-1)*HW + hwbase] = aP;
    }
}

// ---------------------------------------------------------------------------
// 4) 9-tap shifted sum over (h,w): pre[d,h,w] = sum_{kh,kw} B_t[d,h+kh-1,w+kw-1]
// ---------------------------------------------------------------------------
__global__ __launch_bounds__(256) void gathersum_kernel() {
    int w = blockIdx.x*32 + threadIdx.x;
    int h = blockIdx.y*8  + threadIdx.y;
    int d = blockIdx.z;
    float s = 0.f;
    #pragma unroll
    for (int kh = 0; kh < 3; kh++) {
        int hh = h + kh - 1;
        if (hh < 0 || hh >= NH) continue;
        size_t rowb = (size_t)d*HW + (size_t)hh*NW;
        #pragma unroll
        for (int kw = 0; kw < 3; kw++) {
            int ww = w + kw - 1;
            if (ww < 0 || ww >= NW) continue;
            int t = kh*3 + kw;
            s += g_B[(size_t)t*DHW + rowb + ww];
        }
    }
    g_pre[(size_t)d*HW + (size_t)h*NW + w] = s;
}

// ---------------------------------------------------------------------------
// 5) Softmax over D + depth regression + confidence
// ---------------------------------------------------------------------------
__global__ __launch_bounds__(256) void sdc_kernel(const float* __restrict__ dvals,
                                                  float* __restrict__ odepth,
                                                  float* __restrict__ oconf) {
    int idx = blockIdx.x*blockDim.x + threadIdx.x;
    if (idx >= HW) return;
    float p[ND];
    float mx = -1e30f;
    #pragma unroll
    for (int dd = 0; dd < ND; dd++) { p[dd] = g_pre[(size_t)dd*HW + idx]; mx = fmaxf(mx, p[dd]); }
    float s = 0.f;
    #pragma unroll
    for (int dd = 0; dd < ND; dd++) { p[dd] = expf(p[dd] - mx); s += p[dd]; }
    float inv = 1.f / s;
    float depth = 0.f, fi = 0.f;
    #pragma unroll
    for (int dd = 0; dd < ND; dd++) {
        float pr = p[dd] * inv;
        depth += pr * dvals[dd];
        fi    += pr * (float)dd;
    }
    int di = (int)fi;
    di = max(0, min(ND-1, di));
    float conf = 0.f;
    #pragma unroll
    for (int dd = 0; dd < ND; dd++)
        if (dd >= di-1 && dd <= di+2) conf += p[dd] * inv;
    odepth[idx] = depth;
    oconf[idx]  = conf;
}

// ---------------------------------------------------------------------------
// 6) Convex upsample x8
// ---------------------------------------------------------------------------
__global__ __launch_bounds__(256) void upsample_kernel(const float* __restrict__ mask,
                                                       const float* __restrict__ depth,
                                                       float* __restrict__ out) {
    int idx = blockIdx.x*blockDim.x + threadIdx.x;
    if (idx >= RATIO*HW) return;
    int i   = idx / HW;
    int rem = idx - i*HW;
    int h   = rem / NW;
    int w   = rem - h*NW;

    float nb[9];
    #pragma unroll
    for (int dy = 0; dy < 3; dy++)
        #pragma unroll
        for (int dx = 0; dx < 3; dx++) {
            int hh = h + dy - 1, ww = w + dx - 1;
            nb[dy*3+dx] = (hh >= 0 && hh < NH && ww >= 0 && ww < NW) ? depth[hh*NW + ww] : 0.f;
        }

    float val[8];
    #pragma unroll
    for (int j = 0; j < 8; j++) {
        float m[9]; float mx = -1e30f;
        #pragma unroll
        for (int k = 0; k < 9; k++) {
            m[k] = mask[(size_t)((k*8 + i)*8 + j)*HW + rem];
            mx = fmaxf(mx, m[k]);
        }
        float s = 0.f, acc = 0.f;
        #pragma unroll
        for (int k = 0; k < 9; k++) {
            float e = __expf(m[k] - mx);
            s += e; acc += e * nb[k];
        }
        val[j] = acc / s;
    }
    float* o = out + (size_t)(h*8 + i)*(NW*8) + w*8;
    float4* o4 = (float4*)o;
    o4[0] = make_float4(val[0], val[1], val[2], val[3]);
    o4[1] = make_float4(val[4], val[5], val[6], val[7]);
}

// ---------------------------------------------------------------------------
extern "C" void kernel_launch(void* const* d_in, const int* in_sizes, int n_in,
                              void* d_out, int out_size) {
    const float* features = (const float*)d_in[0];  // (V,B,C,H,W)
    const float* proj     = (const float*)d_in[1];  // (B,V,2,4,4)
    const float* dvals    = (const float*)d_in[2];  // (B,D)
    const float* mask     = (const float*)d_in[3];  // (B,576,H,W)
    const float* Wreg     = (const float*)d_in[4];  // (1,C,3,3,3)

    float* out       = (float*)d_out;
    float* out_depth = out + (size_t)NH*RATIO*NW*RATIO;   // after depth_up
    float* out_conf  = out_depth + HW;

    proj_kernel<<<1, 32>>>(proj);                                    // launch 1 (+ctr reset)
    transpose_kernel<<<dim3(NW/32, NH, 2), 256>>>(features, 0);      // launch 2
    transpose_kernel<<<dim3(NW/32, NH, 3), 256>>>(features, 2);      // launch 3
    warpvar_kernel<<<592, 288>>>(dvals, Wreg);                       // launch 4 (ncu slot; 148*4)
    gathersum_kernel<<<dim3(NW/32, NH/8, ND), dim3(32, 8)>>>();      // launch 5
    sdc_kernel<<<HW/256, 256>>>(dvals, out_depth, out_conf);         // launch 6
    upsample_kernel<<<(RATIO*HW)/256, 256>>>(mask, out_depth, out);  // launch 7
}